// round 11
// baseline (speedup 1.0000x reference)
#include <cuda_runtime.h>

// FINN_Burger2D: out = flux(u, a(u)) where a(u) = MLP(1->32->32->1, tanh, no bias)
// Inputs: u[2048*2048] f32, W1[32], W2[32*32], W3[32], D[1], BC[2], stencil[2]
// Output: f32 [2048*2048]
//
// a(u) is scalar->scalar: tabulate {a, da} over [-8,8] (1024 intervals, exact
// tanhf MLP at both interval endpoints per warp). Flux kernel copies the 8KB
// table into SMEM and does ONE random LDS.64 interp per point (bank-conflict
// cost ~5cyc/warp vs ~25 L1 wavefronts for a divergent L1 gather, since u is
// i.i.d. -> lanes hit ~25 distinct lines). Register-rolling 4-row strips keep
// row loads at 1.5x; column neighbors via warp shuffles.

#define NXD 2048
#define NYD 2048
#define TSIZE 1024
#define T_LO (-8.0f)
#define T_HI (8.0f)
#define HROWS 4

__device__ float2 g_tab[TSIZE];   // {a_i, a_{i+1}-a_i}

// ---------------------------------------------------------------------------
// Prologue: one warp per interval; MLP at both endpoints, two interleaved
// accumulators; writes the float2 {a, da} entry directly.
// ---------------------------------------------------------------------------
__global__ __launch_bounds__(256)
void build_table_kernel(const float* __restrict__ W1,
                        const float* __restrict__ W2,
                        const float* __restrict__ W3) {
    __shared__ float h1s[8][2][32];
    const int w    = threadIdx.x >> 5;
    const int lane = threadIdx.x & 31;
    const int node = blockIdx.x * 8 + w;
    if (node >= TSIZE) return;

    const float step = (T_HI - T_LO) / (float)TSIZE;
    const float x0 = T_LO + step * (float)node;
    const float x1 = x0 + step;

    const float w1 = W1[lane];
    h1s[w][0][lane] = tanhf(x0 * w1);
    h1s[w][1][lane] = tanhf(x1 * w1);
    __syncwarp();

    float acc0 = 0.0f, acc1 = 0.0f;
#pragma unroll
    for (int k = 0; k < 32; k++) {
        const float wv = W2[k * 32 + lane];
        acc0 = fmaf(h1s[w][0][k], wv, acc0);
        acc1 = fmaf(h1s[w][1][k], wv, acc1);
    }
    const float w3 = W3[lane];
    float p0 = tanhf(acc0) * w3;
    float p1 = tanhf(acc1) * w3;
#pragma unroll
    for (int o = 16; o > 0; o >>= 1) {
        p0 += __shfl_xor_sync(0xffffffffu, p0, o);
        p1 += __shfl_xor_sync(0xffffffffu, p1, o);
    }
    if (lane == 0) g_tab[node] = make_float2(p0, p1 - p0);
}

// ---------------------------------------------------------------------------
// Main: 2048 blocks x 128 thr. Block = quarter-row (128 chunks) x 4-row band.
// Each thread register-rolls down 4 rows of its fixed float4 column-chunk.
// ---------------------------------------------------------------------------
__global__ __launch_bounds__(128)
void flux_kernel(const float* __restrict__ u,
                 const float* __restrict__ D,
                 const float* __restrict__ BC,
                 const float* __restrict__ st,
                 float* __restrict__ out) {
    __shared__ float2 s_tab[TSIZE];   // 8KB
    {
        const float2* gt = g_tab;
#pragma unroll
        for (int k = 0; k < TSIZE / 128; k++)
            s_tab[k * 128 + threadIdx.x] = gt[k * 128 + threadIdx.x];
    }
    __syncthreads();

    const float d   = D[0];
    const float bc0 = BC[0];
    const float bc1 = BC[1];
    const float s0  = st[0];
    const float s1  = st[1];
    const float inv = 100.0f;                          // 1/DX == 1/DY
    const float scale = (float)TSIZE / (T_HI - T_LO);  // 64

    const int band = blockIdx.x >> 2;          // 0..511 (row band)
    const int q    = blockIdx.x & 3;           // quarter-row
    const int lane = threadIdx.x & 31;
    const int jq   = q * 128 + threadIdx.x;    // chunk column 0..511
    const int col  = jq * 4;
    const int r0   = band * HROWS;

    float4 up, cur;
    if (r0 > 0) up = *(const float4*)(u + (r0 - 1) * NYD + col);
    else        up = make_float4(bc0, bc0, bc0, bc0);
    cur = *(const float4*)(u + r0 * NYD + col);

#pragma unroll
    for (int h = 0; h < HROWS; h++) {
        const int r       = r0 + h;
        const int rowbase = r * NYD + col;

        float4 down;
        if (r < NXD - 1) down = *(const float4*)(u + rowbase + NYD);
        else             down = make_float4(bc1, bc1, bc1, bc1);

        // column-edge scalars from neighbor lanes; real loads only at warp ends
        float um1 = __shfl_up_sync(0xffffffffu, cur.w, 1);    // u[rowbase-1]
        float up4 = __shfl_down_sync(0xffffffffu, cur.x, 1);  // u[rowbase+4]
        if (lane == 0)  um1 = (jq > 0)   ? u[rowbase - 1] : bc0;
        if (lane == 31) up4 = (jq < 511) ? u[rowbase + 4] : bc1;

        const float uin[4] = {cur.x, cur.y, cur.z, cur.w};
        const float uL[4]  = {up.x, up.y, up.z, up.w};          // row i-1 (bc0)
        const float uR[4]  = {down.x, down.y, down.z, down.w};  // row i+1 (bc1)
        const float uB[4]  = {um1, cur.x, cur.y, cur.z};        // col j-1 (bc0)
        const float uT[4]  = {cur.y, cur.z, cur.w, up4};        // col j+1 (bc1)

        float4 o;
        float* op = &o.x;
#pragma unroll
        for (int k = 0; k < 4; k++) {
            const float uv = uin[k];

            // a(u): one random LDS.64 {a, da} + interp
            float t = fmaxf((uv - T_LO) * scale, 0.0f);
            int i0 = (int)t;
            if (i0 > TSIZE - 1) i0 = TSIZE - 1;
            const float fr = t - (float)i0;
            const float2 e = s_tab[i0];
            const float a  = fmaf(fr, e.y, e.x);

            const float cp = fmaf(fmaxf(a, 0.0f),  inv, d);  // d + relu(a)/DX
            const float cm = fmaf(fminf(a, 0.0f), -inv, d);  // d - (-relu(-a))/DX

            const float su2 = 2.0f * s0 * uv;
            const float gLB = fmaf(s1, uL[k] + uB[k], su2);
            const float gRT = fmaf(s1, uR[k] + uT[k], su2);

            op[k] = cp * gLB + cm * gRT;
        }
        *(float4*)(out + rowbase) = o;

        up = cur; cur = down;   // roll the stencil window
    }
}

// ---------------------------------------------------------------------------
extern "C" void kernel_launch(void* const* d_in, const int* in_sizes, int n_in,
                              void* d_out, int out_size) {
    const float* u  = (const float*)d_in[0];
    const float* W1 = (const float*)d_in[1];
    const float* W2 = (const float*)d_in[2];
    const float* W3 = (const float*)d_in[3];
    const float* D  = (const float*)d_in[4];
    const float* BC = (const float*)d_in[5];
    const float* st = (const float*)d_in[6];
    float* out = (float*)d_out;

    (void)in_sizes; (void)n_in; (void)out_size;

    // 1024 intervals, one warp each, 8 warps per block
    build_table_kernel<<<TSIZE / 8, 256>>>(W1, W2, W3);

    // 512 row-bands x 4 quarter-rows
    flux_kernel<<<(NXD / HROWS) * 4, 128>>>(u, D, BC, st, out);
}

// round 12
// speedup vs baseline: 1.0860x; 1.0860x over previous
#include <cuda_runtime.h>

// FINN_Burger2D: out = flux(u, a(u)) where a(u) = MLP(1->32->32->1, tanh, no bias)
// Inputs: u[2048*2048] f32, W1[32], W2[32*32], W3[32], D[1], BC[2], stencil[2]
// Output: f32 [2048*2048]
//
// a(u) is scalar->scalar: tabulate {a, da} over [-8,8] (512 intervals, exact
// tanhf MLP at both endpoints per warp). Flux blocks copy the 4KB table into
// SMEM once (amortized over a 256-thr x 4-row half-row tile) and do ONE random
// LDS.64 interp per point. Register-rolling strips keep row loads at 1.5x;
// column neighbors via warp shuffles.

#define NXD 2048
#define NYD 2048
#define TSIZE 512
#define T_LO (-8.0f)
#define T_HI (8.0f)
#define HROWS 4

__device__ float2 g_tab[TSIZE];   // {a_i, a_{i+1}-a_i}

// ---------------------------------------------------------------------------
// Prologue: one warp per interval; MLP at both endpoints, two interleaved
// accumulators; writes the float2 {a, da} entry directly.
// ---------------------------------------------------------------------------
__global__ __launch_bounds__(256)
void build_table_kernel(const float* __restrict__ W1,
                        const float* __restrict__ W2,
                        const float* __restrict__ W3) {
    __shared__ float h1s[8][2][32];
    const int w    = threadIdx.x >> 5;
    const int lane = threadIdx.x & 31;
    const int node = blockIdx.x * 8 + w;
    if (node >= TSIZE) return;

    const float step = (T_HI - T_LO) / (float)TSIZE;
    const float x0 = T_LO + step * (float)node;
    const float x1 = x0 + step;

    const float w1 = W1[lane];
    h1s[w][0][lane] = tanhf(x0 * w1);
    h1s[w][1][lane] = tanhf(x1 * w1);
    __syncwarp();

    float acc0 = 0.0f, acc1 = 0.0f;
#pragma unroll
    for (int k = 0; k < 32; k++) {
        const float wv = W2[k * 32 + lane];
        acc0 = fmaf(h1s[w][0][k], wv, acc0);
        acc1 = fmaf(h1s[w][1][k], wv, acc1);
    }
    const float w3 = W3[lane];
    float p0 = tanhf(acc0) * w3;
    float p1 = tanhf(acc1) * w3;
#pragma unroll
    for (int o = 16; o > 0; o >>= 1) {
        p0 += __shfl_xor_sync(0xffffffffu, p0, o);
        p1 += __shfl_xor_sync(0xffffffffu, p1, o);
    }
    if (lane == 0) g_tab[node] = make_float2(p0, p1 - p0);
}

// ---------------------------------------------------------------------------
// Main: 1024 blocks x 256 thr. Block = half-row (256 chunks) x 4-row band.
// Each thread register-rolls down 4 rows of its fixed float4 column-chunk.
// ---------------------------------------------------------------------------
__global__ __launch_bounds__(256)
void flux_kernel(const float* __restrict__ u,
                 const float* __restrict__ D,
                 const float* __restrict__ BC,
                 const float* __restrict__ st,
                 float* __restrict__ out) {
    __shared__ float2 s_tab[TSIZE];   // 4KB
    {
        const float2* gt = g_tab;
#pragma unroll
        for (int k = 0; k < TSIZE / 256; k++)
            s_tab[k * 256 + threadIdx.x] = __ldg(&gt[k * 256 + threadIdx.x]);
    }
    __syncthreads();

    const float d   = D[0];
    const float bc0 = BC[0];
    const float bc1 = BC[1];
    const float s0  = st[0];
    const float s1  = st[1];
    const float inv = 100.0f;                          // 1/DX == 1/DY
    const float scale = (float)TSIZE / (T_HI - T_LO);  // 32

    const int band = blockIdx.x >> 1;          // 0..511 (row band)
    const int half = blockIdx.x & 1;           // half-row
    const int lane = threadIdx.x & 31;
    const int jq   = half * 256 + threadIdx.x; // chunk column 0..511
    const int col  = jq * 4;
    const int r0   = band * HROWS;

    float4 up, cur;
    if (r0 > 0) up = *(const float4*)(u + (r0 - 1) * NYD + col);
    else        up = make_float4(bc0, bc0, bc0, bc0);
    cur = *(const float4*)(u + r0 * NYD + col);

#pragma unroll
    for (int h = 0; h < HROWS; h++) {
        const int r       = r0 + h;
        const int rowbase = r * NYD + col;

        float4 down;
        if (r < NXD - 1) down = *(const float4*)(u + rowbase + NYD);
        else             down = make_float4(bc1, bc1, bc1, bc1);

        // column-edge scalars from neighbor lanes; real loads only at warp ends
        float um1 = __shfl_up_sync(0xffffffffu, cur.w, 1);    // u[rowbase-1]
        float up4 = __shfl_down_sync(0xffffffffu, cur.x, 1);  // u[rowbase+4]
        if (lane == 0)  um1 = (jq > 0)   ? u[rowbase - 1] : bc0;
        if (lane == 31) up4 = (jq < 511) ? u[rowbase + 4] : bc1;

        const float uin[4] = {cur.x, cur.y, cur.z, cur.w};
        const float uL[4]  = {up.x, up.y, up.z, up.w};          // row i-1 (bc0)
        const float uR[4]  = {down.x, down.y, down.z, down.w};  // row i+1 (bc1)
        const float uB[4]  = {um1, cur.x, cur.y, cur.z};        // col j-1 (bc0)
        const float uT[4]  = {cur.y, cur.z, cur.w, up4};        // col j+1 (bc1)

        float4 o;
        float* op = &o.x;
#pragma unroll
        for (int k = 0; k < 4; k++) {
            const float uv = uin[k];

            // a(u): one random LDS.64 {a, da} + interp
            float t = fmaxf((uv - T_LO) * scale, 0.0f);
            int i0 = (int)t;
            if (i0 > TSIZE - 1) i0 = TSIZE - 1;
            const float fr = t - (float)i0;
            const float2 e = s_tab[i0];
            const float a  = fmaf(fr, e.y, e.x);

            const float cp = fmaf(fmaxf(a, 0.0f),  inv, d);  // d + relu(a)/DX
            const float cm = fmaf(fminf(a, 0.0f), -inv, d);  // d - (-relu(-a))/DX

            const float su2 = 2.0f * s0 * uv;
            const float gLB = fmaf(s1, uL[k] + uB[k], su2);
            const float gRT = fmaf(s1, uR[k] + uT[k], su2);

            op[k] = cp * gLB + cm * gRT;
        }
        *(float4*)(out + rowbase) = o;

        up = cur; cur = down;   // roll the stencil window
    }
}

// ---------------------------------------------------------------------------
extern "C" void kernel_launch(void* const* d_in, const int* in_sizes, int n_in,
                              void* d_out, int out_size) {
    const float* u  = (const float*)d_in[0];
    const float* W1 = (const float*)d_in[1];
    const float* W2 = (const float*)d_in[2];
    const float* W3 = (const float*)d_in[3];
    const float* D  = (const float*)d_in[4];
    const float* BC = (const float*)d_in[5];
    const float* st = (const float*)d_in[6];
    float* out = (float*)d_out;

    (void)in_sizes; (void)n_in; (void)out_size;

    // 512 intervals, one warp each, 8 warps per block
    build_table_kernel<<<TSIZE / 8, 256>>>(W1, W2, W3);

    // 512 row-bands x 2 half-rows
    flux_kernel<<<(NXD / HROWS) * 2, 256>>>(u, D, BC, st, out);
}

// round 13
// speedup vs baseline: 1.1050x; 1.0175x over previous
#include <cuda_runtime.h>

// FINN_Burger2D: out = flux(u, a(u)) where a(u) = MLP(1->32->32->1, tanh, no bias)
// Inputs: u[2048*2048] f32, W1[32], W2[32*32], W3[32], D[1], BC[2], stencil[2]
// Output: f32 [2048*2048]
//
// a(u) is scalar->scalar: tabulate {a, da} over [-8,8] (512 intervals, exact
// tanhf MLP at both endpoints per warp). Flux blocks copy the 4KB table into
// SMEM once and do ONE random LDS.64 interp per point. All 6 row-vectors of a
// 4-row band (plus edge scalars) are FRONT-BATCHED at block entry so L2 latency
// is paid once (MLP~6-8), then the flux math runs from registers.

#define NXD 2048
#define NYD 2048
#define TSIZE 512
#define T_LO (-8.0f)
#define T_HI (8.0f)
#define HROWS 4

__device__ float2 g_tab[TSIZE];   // {a_i, a_{i+1}-a_i}

// ---------------------------------------------------------------------------
// Prologue: one warp per interval; MLP at both endpoints, two interleaved
// accumulators; writes the float2 {a, da} entry directly.
// ---------------------------------------------------------------------------
__global__ __launch_bounds__(256)
void build_table_kernel(const float* __restrict__ W1,
                        const float* __restrict__ W2,
                        const float* __restrict__ W3) {
    __shared__ float h1s[8][2][32];
    const int w    = threadIdx.x >> 5;
    const int lane = threadIdx.x & 31;
    const int node = blockIdx.x * 8 + w;
    if (node >= TSIZE) return;

    const float step = (T_HI - T_LO) / (float)TSIZE;
    const float x0 = T_LO + step * (float)node;
    const float x1 = x0 + step;

    const float w1 = W1[lane];
    h1s[w][0][lane] = tanhf(x0 * w1);
    h1s[w][1][lane] = tanhf(x1 * w1);
    __syncwarp();

    float acc0 = 0.0f, acc1 = 0.0f;
#pragma unroll
    for (int k = 0; k < 32; k++) {
        const float wv = W2[k * 32 + lane];
        acc0 = fmaf(h1s[w][0][k], wv, acc0);
        acc1 = fmaf(h1s[w][1][k], wv, acc1);
    }
    const float w3 = W3[lane];
    float p0 = tanhf(acc0) * w3;
    float p1 = tanhf(acc1) * w3;
#pragma unroll
    for (int o = 16; o > 0; o >>= 1) {
        p0 += __shfl_xor_sync(0xffffffffu, p0, o);
        p1 += __shfl_xor_sync(0xffffffffu, p1, o);
    }
    if (lane == 0) g_tab[node] = make_float2(p0, p1 - p0);
}

// ---------------------------------------------------------------------------
// Main: 1024 blocks x 256 thr. Block = half-row (256 chunks) x 4-row band.
// Front-batched loads: all 6 rows + 8 edge scalars issued before any math.
// ---------------------------------------------------------------------------
__global__ __launch_bounds__(256, 4)
void flux_kernel(const float* __restrict__ u,
                 const float* __restrict__ D,
                 const float* __restrict__ BC,
                 const float* __restrict__ st,
                 float* __restrict__ out) {
    __shared__ float2 s_tab[TSIZE];   // 4KB
    {
        const float2* gt = g_tab;
#pragma unroll
        for (int k = 0; k < TSIZE / 256; k++)
            s_tab[k * 256 + threadIdx.x] = __ldg(&gt[k * 256 + threadIdx.x]);
    }

    const float d   = D[0];
    const float bc0 = BC[0];
    const float bc1 = BC[1];
    const float s0  = st[0];
    const float s1  = st[1];
    const float inv = 100.0f;                          // 1/DX == 1/DY
    const float scale = (float)TSIZE / (T_HI - T_LO);  // 32

    const int band = blockIdx.x >> 1;          // 0..511 (row band)
    const int half = blockIdx.x & 1;           // half-row
    const int lane = threadIdx.x & 31;
    const int jq   = half * 256 + threadIdx.x; // chunk column 0..511
    const int col  = jq * 4;
    const int r0   = band * HROWS;
    const long base0 = (long)r0 * NYD + col;

    // ---- front-batched loads: rows r0-1 .. r0+HROWS, plus edge scalars ----
    float4 row[HROWS + 2];
    if (r0 > 0) row[0] = *(const float4*)(u + base0 - NYD);
    else        row[0] = make_float4(bc0, bc0, bc0, bc0);
#pragma unroll
    for (int h = 0; h < HROWS; h++)
        row[h + 1] = *(const float4*)(u + base0 + h * NYD);
    if (r0 + HROWS < NXD) row[HROWS + 1] = *(const float4*)(u + base0 + HROWS * NYD);
    else                  row[HROWS + 1] = make_float4(bc1, bc1, bc1, bc1);

    float eA[HROWS], eB[HROWS];   // u[rowbase-1] (lane0), u[rowbase+4] (lane31)
#pragma unroll
    for (int h = 0; h < HROWS; h++) {
        eA[h] = bc0;
        eB[h] = bc1;
        if (lane == 0  && jq > 0)   eA[h] = u[base0 + h * NYD - 1];
        if (lane == 31 && jq < 511) eB[h] = u[base0 + h * NYD + 4];
    }

    __syncthreads();   // table ready (also after all loads are in flight)

    // ---- compute all HROWS rows from registers ----
#pragma unroll
    for (int h = 0; h < HROWS; h++) {
        const float4 up   = row[h];
        const float4 cur  = row[h + 1];
        const float4 down = row[h + 2];

        float um1 = __shfl_up_sync(0xffffffffu, cur.w, 1);
        float up4 = __shfl_down_sync(0xffffffffu, cur.x, 1);
        if (lane == 0)  um1 = eA[h];
        if (lane == 31) up4 = eB[h];

        const float uin[4] = {cur.x, cur.y, cur.z, cur.w};
        const float uL[4]  = {up.x, up.y, up.z, up.w};          // row i-1 (bc0)
        const float uR[4]  = {down.x, down.y, down.z, down.w};  // row i+1 (bc1)
        const float uB[4]  = {um1, cur.x, cur.y, cur.z};        // col j-1 (bc0)
        const float uT[4]  = {cur.y, cur.z, cur.w, up4};        // col j+1 (bc1)

        float4 o;
        float* op = &o.x;
#pragma unroll
        for (int k = 0; k < 4; k++) {
            const float uv = uin[k];

            // a(u): one random LDS.64 {a, da} + interp
            float t = fmaxf((uv - T_LO) * scale, 0.0f);
            int i0 = (int)t;
            if (i0 > TSIZE - 1) i0 = TSIZE - 1;
            const float fr = t - (float)i0;
            const float2 e = s_tab[i0];
            const float a  = fmaf(fr, e.y, e.x);

            const float cp = fmaf(fmaxf(a, 0.0f),  inv, d);  // d + relu(a)/DX
            const float cm = fmaf(fminf(a, 0.0f), -inv, d);  // d - (-relu(-a))/DX

            const float su2 = 2.0f * s0 * uv;
            const float gLB = fmaf(s1, uL[k] + uB[k], su2);
            const float gRT = fmaf(s1, uR[k] + uT[k], su2);

            op[k] = cp * gLB + cm * gRT;
        }
        *(float4*)(out + base0 + h * NYD) = o;
    }
}

// ---------------------------------------------------------------------------
extern "C" void kernel_launch(void* const* d_in, const int* in_sizes, int n_in,
                              void* d_out, int out_size) {
    const float* u  = (const float*)d_in[0];
    const float* W1 = (const float*)d_in[1];
    const float* W2 = (const float*)d_in[2];
    const float* W3 = (const float*)d_in[3];
    const float* D  = (const float*)d_in[4];
    const float* BC = (const float*)d_in[5];
    const float* st = (const float*)d_in[6];
    float* out = (float*)d_out;

    (void)in_sizes; (void)n_in; (void)out_size;

    // 512 intervals, one warp each, 8 warps per block
    build_table_kernel<<<TSIZE / 8, 256>>>(W1, W2, W3);

    // 512 row-bands x 2 half-rows
    flux_kernel<<<(NXD / HROWS) * 2, 256>>>(u, D, BC, st, out);
}